// round 2
// baseline (speedup 1.0000x reference)
#include <cuda_runtime.h>

// MinimalRNNCell: y[b,t,:] = states[b,t,:] @ CyT
//   states[b,t,:] = Ky[b,t,:] + states[b,t-1,:] @ AT  (states[-1]=0)
//   Ky = x @ KT
// B=64, T=4096, NIN=64, U=128, NOUT=64. All fp32.
//
// K1: Ky = x@KT          (tiled fp32 GEMM, parallel)
// K2: serial recurrence  (1 CTA per batch row, A in registers as f32x2 pairs,
//                         v double-buffered in smem, 1 bar/step)
// K3: y = states@CyT     (tiled fp32 GEMM, parallel)

#define DEV_INLINE __device__ __forceinline__

constexpr int Bc   = 64;
constexpr int Tc   = 4096;
constexpr int NIN  = 64;
constexpr int UNI  = 128;
constexpr int NOUT = 64;
constexpr int BT   = Bc * Tc;  // 262144

// Scratch (allowed: __device__ globals, no cudaMalloc)
__device__ float g_Ky[(size_t)BT * UNI];      // 134 MB
__device__ float g_states[(size_t)BT * UNI];  // 134 MB

// ---------------- f32x2 helpers (FFMA2 is PTX-only) ----------------
DEV_INLINE unsigned long long pack2(float lo, float hi) {
    unsigned long long d;
    asm("mov.b64 %0, {%1, %2};" : "=l"(d) : "f"(lo), "f"(hi));
    return d;
}
DEV_INLINE void fma2(unsigned long long& d, unsigned long long a, unsigned long long b) {
    asm("fma.rn.f32x2 %0, %1, %2, %0;" : "+l"(d) : "l"(a), "l"(b));
}
DEV_INLINE unsigned long long add2(unsigned long long a, unsigned long long b) {
    unsigned long long d;
    asm("add.rn.f32x2 %0, %1, %2;" : "=l"(d) : "l"(a), "l"(b));
    return d;
}
DEV_INLINE void unpack2(unsigned long long v, float& lo, float& hi) {
    asm("mov.b64 {%0, %1}, %2;" : "=f"(lo), "=f"(hi) : "l"(v));
}

// ---------------- K1: Ky[BT,128] = x[BT,64] @ KT[64,128] ----------------
// grid (BT/64, 128/64), 256 threads, 64x64 tile, 4x4 microtile
__global__ void __launch_bounds__(256) k_in_gemm(const float* __restrict__ x,
                                                 const float* __restrict__ KT) {
    __shared__ float Xs[64][65];
    __shared__ float Ws[64][64];
    const int m0  = blockIdx.x * 64;
    const int n0  = blockIdx.y * 64;
    const int tid = threadIdx.x;

    for (int i = tid; i < 64 * 64; i += 256) {
        int r = i >> 6, c = i & 63;
        Xs[r][c] = x[(size_t)(m0 + r) * NIN + c];
        Ws[r][c] = KT[r * UNI + n0 + c];
    }
    __syncthreads();

    const int ty = tid >> 4, tx = tid & 15;
    float acc[4][4] = {};
#pragma unroll
    for (int k = 0; k < 64; k++) {
        float4 w = *(const float4*)&Ws[k][tx * 4];
#pragma unroll
        for (int i = 0; i < 4; i++) {
            float a = Xs[ty * 4 + i][k];
            acc[i][0] += a * w.x;
            acc[i][1] += a * w.y;
            acc[i][2] += a * w.z;
            acc[i][3] += a * w.w;
        }
    }
#pragma unroll
    for (int i = 0; i < 4; i++) {
        float4 o = make_float4(acc[i][0], acc[i][1], acc[i][2], acc[i][3]);
        *(float4*)&g_Ky[(size_t)(m0 + ty * 4 + i) * UNI + n0 + tx * 4] = o;
    }
}

// ---------------- K2: serial recurrence ----------------
// 64 CTAs (one batch row each), 128 threads. Thread u owns state column u.
// A column u lives in registers as 64 packed (row-pair) f32x2 values.
// v broadcast via double-buffered smem; one __syncthreads per step.
__global__ void __launch_bounds__(128) k_recur(const float* __restrict__ AT) {
    __shared__ __align__(16) float vbuf[2][UNI];
    const int u = threadIdx.x;
    const int b = blockIdx.x;

    unsigned long long a2[64];
#pragma unroll
    for (int j = 0; j < 64; j++)
        a2[j] = pack2(AT[(2 * j) * UNI + u], AT[(2 * j + 1) * UNI + u]);

    const float* kyp = g_Ky + (size_t)b * Tc * UNI + u;
    float*       sp  = g_states + (size_t)b * Tc * UNI + u;

    vbuf[0][u] = 0.0f;
    float kycur = kyp[0];
    __syncthreads();

    for (int t = 0; t < Tc; t++) {
        // prefetch next ky early; its latency hides under the FMA block
        const int tn   = (t + 1 < Tc) ? (t + 1) : t;
        float kynext   = kyp[(size_t)tn * UNI];

        const ulonglong2* vp = reinterpret_cast<const ulonglong2*>(vbuf[t & 1]);
        unsigned long long acc0 = 0ull, acc1 = 0ull, accA = 0ull, accB = 0ull;
#pragma unroll
        for (int q = 0; q < 32; q += 4) {
            ulonglong2 v0 = vp[q + 0];
            ulonglong2 v1 = vp[q + 1];
            ulonglong2 v2 = vp[q + 2];
            ulonglong2 v3 = vp[q + 3];
            fma2(acc0, v0.x, a2[2 * q + 0]); fma2(acc0, v0.y, a2[2 * q + 1]);
            fma2(acc1, v1.x, a2[2 * q + 2]); fma2(acc1, v1.y, a2[2 * q + 3]);
            fma2(accA, v2.x, a2[2 * q + 4]); fma2(accA, v2.y, a2[2 * q + 5]);
            fma2(accB, v3.x, a2[2 * q + 6]); fma2(accB, v3.y, a2[2 * q + 7]);
        }
        unsigned long long s = add2(add2(acc0, acc1), add2(accA, accB));
        float lo, hi;
        unpack2(s, lo, hi);
        float nv = kycur + lo + hi;

        sp[(size_t)t * UNI]     = nv;        // states[b,t,u]
        vbuf[(t & 1) ^ 1][u]    = nv;        // broadcast for next step
        kycur = kynext;
        __syncthreads();
    }
}

// ---------------- K3: y[BT,64] = states[BT,128] @ CyT[128,64] ----------------
// grid BT/64, 256 threads, 64x64 tile, K split in two 64-chunks
__global__ void __launch_bounds__(256) k_out_gemm(const float* __restrict__ CyT,
                                                  float* __restrict__ y) {
    __shared__ float Xs[64][65];
    __shared__ float Ws[64][64];
    const int m0  = blockIdx.x * 64;
    const int tid = threadIdx.x;
    const int ty  = tid >> 4, tx = tid & 15;

    float acc[4][4] = {};
#pragma unroll 1
    for (int kt = 0; kt < 2; kt++) {
        __syncthreads();
        for (int i = tid; i < 64 * 64; i += 256) {
            int r = i >> 6, c = i & 63;
            Xs[r][c] = g_states[(size_t)(m0 + r) * UNI + kt * 64 + c];
            Ws[r][c] = CyT[(kt * 64 + r) * NOUT + c];
        }
        __syncthreads();
#pragma unroll
        for (int k = 0; k < 64; k++) {
            float4 w = *(const float4*)&Ws[k][tx * 4];
#pragma unroll
            for (int i = 0; i < 4; i++) {
                float a = Xs[ty * 4 + i][k];
                acc[i][0] += a * w.x;
                acc[i][1] += a * w.y;
                acc[i][2] += a * w.z;
                acc[i][3] += a * w.w;
            }
        }
    }
#pragma unroll
    for (int i = 0; i < 4; i++) {
        float4 o = make_float4(acc[i][0], acc[i][1], acc[i][2], acc[i][3]);
        *(float4*)&y[(size_t)(m0 + ty * 4 + i) * NOUT + tx * 4] = o;
    }
}

// ---------------- launch ----------------
extern "C" void kernel_launch(void* const* d_in, const int* in_sizes, int n_in,
                              void* d_out, int out_size) {
    const float* x   = (const float*)d_in[0];  // [64,4096,64]
    const float* AT  = (const float*)d_in[1];  // [128,128]
    const float* KT  = (const float*)d_in[2];  // [64,128]
    const float* CyT = (const float*)d_in[3];  // [128,64]
    float*       y   = (float*)d_out;          // [64,4096,64]

    dim3 g1(BT / 64, UNI / 64);
    k_in_gemm<<<g1, 256>>>(x, KT);
    k_recur<<<Bc, 128>>>(AT);
    k_out_gemm<<<BT / 64, 256>>>(CyT, y);
}

// round 6
// speedup vs baseline: 2.1702x; 2.1702x over previous
#include <cuda_runtime.h>

// MinimalRNNCell via chunked scan, R=64.
//   s[t] = ky[t] + s[t-1]@A          (A := AT input, row-vector convention)
//   y[t] = s[t]@CyT
// Chunk c covers t = c*64 .. c*64+63.
//   sl[c,r]  : local scan with zero init         (k_local, 4096 parallel chunks)
//   e[c]     = s[c*64 - 1]; e[0]=0; e[c+1] = sl[c,63] + e[c]@A^64   (k_boundary)
//   y[c*64+r] = sl[c,r]@CyT + e[c]@G[r],  G[r] = A^(r+1)@CyT        (k_fix + k_out)
// G and A^64 built by log-doubling GEMMs.

#define DEV_INLINE __device__ __forceinline__

constexpr int Bc   = 64;
constexpr int Tc   = 4096;
constexpr int NIN  = 64;
constexpr int UNI  = 128;
constexpr int NOUT = 64;
constexpr int R    = 64;
constexpr int NC   = Tc / R;        // 64 chunks per batch row
constexpr int BT   = Bc * Tc;       // 262144
constexpr int BCn  = Bc * NC;       // 4096 (b,c) pairs

// -------- device scratch (no cudaMalloc allowed) --------
__device__ float g_Ky[(size_t)BT * UNI];        // 134 MB
__device__ float g_sl[(size_t)BT * UNI];        // 134 MB  (local states)
__device__ float g_slend[(size_t)BCn * UNI];    // 2 MB    sl[c, R-1]
__device__ float g_e[(size_t)BCn * UNI];        // 2 MB    e[b,c]
__device__ float g_F[(size_t)BCn * (R * NOUT)]; // 64 MB   e@G2
__device__ float g_G2[(size_t)UNI * (R * NOUT)];// 2 MB    G2[i][r*64+o]
__device__ float g_P2[UNI * UNI], g_P4[UNI * UNI], g_P8[UNI * UNI],
                 g_P16[UNI * UNI], g_P32[UNI * UNI], g_P64[UNI * UNI];

// -------- f32x2 helpers --------
DEV_INLINE unsigned long long pack2(float lo, float hi) {
    unsigned long long d;
    asm("mov.b64 %0, {%1, %2};" : "=l"(d) : "f"(lo), "f"(hi));
    return d;
}
DEV_INLINE void fma2(unsigned long long& d, unsigned long long a, unsigned long long b) {
    asm("fma.rn.f32x2 %0, %1, %2, %0;" : "+l"(d) : "l"(a), "l"(b));
}
DEV_INLINE unsigned long long add2(unsigned long long a, unsigned long long b) {
    unsigned long long d;
    asm("add.rn.f32x2 %0, %1, %2;" : "=l"(d) : "l"(a), "l"(b));
    return d;
}
DEV_INLINE void unpack2(unsigned long long v, float& lo, float& hi) {
    asm("mov.b64 {%0, %1}, %2;" : "=f"(lo), "=f"(hi) : "l"(v));
}

// 128-thread warpgroup dot helper: nv = extra + vbuf @ Acol(u), A in regs.
DEV_INLINE float dot128(const float* vbuf, const unsigned long long* a2, float extra) {
    const ulonglong2* vp = reinterpret_cast<const ulonglong2*>(vbuf);
    unsigned long long acc0 = 0ull, acc1 = 0ull, accA = 0ull, accB = 0ull;
#pragma unroll
    for (int q = 0; q < 32; q += 4) {
        ulonglong2 v0 = vp[q + 0];
        ulonglong2 v1 = vp[q + 1];
        ulonglong2 v2 = vp[q + 2];
        ulonglong2 v3 = vp[q + 3];
        fma2(acc0, v0.x, a2[2 * q + 0]); fma2(acc0, v0.y, a2[2 * q + 1]);
        fma2(acc1, v1.x, a2[2 * q + 2]); fma2(acc1, v1.y, a2[2 * q + 3]);
        fma2(accA, v2.x, a2[2 * q + 4]); fma2(accA, v2.y, a2[2 * q + 5]);
        fma2(accB, v3.x, a2[2 * q + 6]); fma2(accB, v3.y, a2[2 * q + 7]);
    }
    unsigned long long s = add2(add2(acc0, acc1), add2(accA, accB));
    float lo, hi;
    unpack2(s, lo, hi);
    return extra + lo + hi;
}

// ---------------- K1: Ky[BT,128] = x[BT,64] @ KT[64,128] ----------------
__global__ void __launch_bounds__(256) k_in_gemm(const float* __restrict__ x,
                                                 const float* __restrict__ KT) {
    __shared__ float XsT[64][68];   // transposed: [k][m], rows 272B (16B aligned)
    __shared__ float Ws[64][64];
    const int m0  = blockIdx.x * 64;
    const int n0  = blockIdx.y * 64;
    const int tid = threadIdx.x;

    for (int i = tid; i < 64 * 64; i += 256) {
        int r = i >> 6, c = i & 63;
        XsT[c][r] = x[(size_t)(m0 + r) * NIN + c];
        Ws[r][c]  = KT[r * UNI + n0 + c];
    }
    __syncthreads();

    const int ty = tid >> 4, tx = tid & 15;
    float acc[4][4] = {};
#pragma unroll
    for (int k = 0; k < 64; k++) {
        float4 a = *(const float4*)&XsT[k][ty * 4];
        float4 w = *(const float4*)&Ws[k][tx * 4];
        acc[0][0] += a.x * w.x; acc[0][1] += a.x * w.y; acc[0][2] += a.x * w.z; acc[0][3] += a.x * w.w;
        acc[1][0] += a.y * w.x; acc[1][1] += a.y * w.y; acc[1][2] += a.y * w.z; acc[1][3] += a.y * w.w;
        acc[2][0] += a.z * w.x; acc[2][1] += a.z * w.y; acc[2][2] += a.z * w.z; acc[2][3] += a.z * w.w;
        acc[3][0] += a.w * w.x; acc[3][1] += a.w * w.y; acc[3][2] += a.w * w.z; acc[3][3] += a.w * w.w;
    }
#pragma unroll
    for (int i = 0; i < 4; i++) {
        float4 o = make_float4(acc[i][0], acc[i][1], acc[i][2], acc[i][3]);
        *(float4*)&g_Ky[(size_t)(m0 + ty * 4 + i) * UNI + n0 + tx * 4] = o;
    }
}

// ------- generic C[64-tile] = L[M x 128 (ld=128)] @ B[128 x N (ldB)] -------
// grid.x = N/64 tiles, grid.y = M/64 tiles. K = 128 fixed. 256 threads.
__global__ void __launch_bounds__(256) gemm_ld(const float* __restrict__ L,
                                               const float* __restrict__ B, int ldB,
                                               float* __restrict__ C, int ldC) {
    __shared__ float XsT[64][68];
    __shared__ float Ws[64][64];
    const int n0  = blockIdx.x * 64;
    const int m0  = blockIdx.y * 64;
    const int tid = threadIdx.x;
    const int ty = tid >> 4, tx = tid & 15;

    float acc[4][4] = {};
#pragma unroll 1
    for (int kk = 0; kk < 2; kk++) {
        __syncthreads();
        for (int i = tid; i < 64 * 64; i += 256) {
            int r = i >> 6, c = i & 63;
            XsT[c][r] = L[(size_t)(m0 + r) * 128 + kk * 64 + c];
            Ws[r][c]  = B[(size_t)(kk * 64 + r) * ldB + n0 + c];
        }
        __syncthreads();
#pragma unroll
        for (int k = 0; k < 64; k++) {
            float4 a = *(const float4*)&XsT[k][ty * 4];
            float4 w = *(const float4*)&Ws[k][tx * 4];
            acc[0][0] += a.x * w.x; acc[0][1] += a.x * w.y; acc[0][2] += a.x * w.z; acc[0][3] += a.x * w.w;
            acc[1][0] += a.y * w.x; acc[1][1] += a.y * w.y; acc[1][2] += a.y * w.z; acc[1][3] += a.y * w.w;
            acc[2][0] += a.z * w.x; acc[2][1] += a.z * w.y; acc[2][2] += a.z * w.z; acc[2][3] += a.z * w.w;
            acc[3][0] += a.w * w.x; acc[3][1] += a.w * w.y; acc[3][2] += a.w * w.z; acc[3][3] += a.w * w.w;
        }
    }
#pragma unroll
    for (int i = 0; i < 4; i++) {
        float4 o = make_float4(acc[i][0], acc[i][1], acc[i][2], acc[i][3]);
        *(float4*)&C[(size_t)(m0 + ty * 4 + i) * ldC + n0 + tx * 4] = o;
    }
}

// ---------------- k_local: per-chunk local scan ----------------
// grid = 4096 (bc), 128 threads. A in regs, v broadcast via smem, ky ring=4.
__global__ void __launch_bounds__(128) k_local(const float* __restrict__ AT) {
    __shared__ __align__(16) float vbuf[2][UNI];
    const int u  = threadIdx.x;
    const int bc = blockIdx.x;

    unsigned long long a2[64];
#pragma unroll
    for (int j = 0; j < 64; j++)
        a2[j] = pack2(AT[(2 * j) * UNI + u], AT[(2 * j + 1) * UNI + u]);

    const float* kyp = g_Ky + (size_t)bc * R * UNI + u;
    float*       sp  = g_sl + (size_t)bc * R * UNI + u;

    float ring[4];
#pragma unroll
    for (int p = 0; p < 4; p++) ring[p] = kyp[(size_t)p * UNI];

    vbuf[0][u] = 0.0f;
    __syncthreads();

#pragma unroll 1
    for (int rr = 0; rr < R / 4; rr++) {
#pragma unroll
        for (int p = 0; p < 4; p++) {
            const int r = rr * 4 + p;
            float kycur = ring[p];
            if (r + 4 < R) ring[p] = kyp[(size_t)(r + 4) * UNI];

            float nv = dot128(vbuf[r & 1], a2, kycur);
            sp[(size_t)r * UNI]  = nv;
            vbuf[(r & 1) ^ 1][u] = nv;
            if (r == R - 1) g_slend[(size_t)bc * UNI + u] = nv;
            __syncthreads();
        }
    }
}

// ---------------- k_boundary: e-scan across chunks ----------------
// grid = 64 (b), 128 threads. P64 in regs. 64 cheap serial steps.
__global__ void __launch_bounds__(128) k_boundary() {
    __shared__ __align__(16) float vbuf[2][UNI];
    const int u = threadIdx.x;
    const int b = blockIdx.x;

    unsigned long long a2[64];
#pragma unroll
    for (int j = 0; j < 64; j++)
        a2[j] = pack2(g_P64[(2 * j) * UNI + u], g_P64[(2 * j + 1) * UNI + u]);

    const float* slend = g_slend + (size_t)b * NC * UNI + u;
    float*       ep    = g_e     + (size_t)b * NC * UNI + u;

    ep[0]      = 0.0f;   // e[b,0] = 0
    vbuf[0][u] = 0.0f;
    float secur = slend[0];
    __syncthreads();

#pragma unroll 1
    for (int c = 1; c < NC; c++) {
        float senext = (c < NC - 1) ? slend[(size_t)c * UNI] : 0.0f;
        float nv = dot128(vbuf[(c - 1) & 1], a2, secur);   // e[c] = slend[c-1] + e[c-1]@P64
        ep[(size_t)c * UNI]      = nv;
        vbuf[c & 1][u]           = nv;
        secur = senext;
        __syncthreads();
    }
}

// ---------------- k_out: y = sl@CyT + F ----------------
// grid = 4096 (64-row tiles of BT), 256 threads.
__global__ void __launch_bounds__(256) k_out(const float* __restrict__ CyT,
                                             float* __restrict__ y) {
    __shared__ float XsT[64][68];
    __shared__ float Ws[64][64];
    const int m0  = blockIdx.x * 64;
    const int tid = threadIdx.x;
    const int ty = tid >> 4, tx = tid & 15;

    const int b    = m0 >> 12;           // /T
    const int t0   = m0 & (Tc - 1);
    const int frow = (b << 6) | (t0 >> 6);
    const float* Fr = g_F + (size_t)frow * (R * NOUT);

    float acc[4][4] = {};
#pragma unroll 1
    for (int kk = 0; kk < 2; kk++) {
        __syncthreads();
        for (int i = tid; i < 64 * 64; i += 256) {
            int r = i >> 6, c = i & 63;
            XsT[c][r] = g_sl[(size_t)(m0 + r) * UNI + kk * 64 + c];
            Ws[r][c]  = CyT[(kk * 64 + r) * NOUT + c];
        }
        __syncthreads();
#pragma unroll
        for (int k = 0; k < 64; k++) {
            float4 a = *(const float4*)&XsT[k][ty * 4];
            float4 w = *(const float4*)&Ws[k][tx * 4];
            acc[0][0] += a.x * w.x; acc[0][1] += a.x * w.y; acc[0][2] += a.x * w.z; acc[0][3] += a.x * w.w;
            acc[1][0] += a.y * w.x; acc[1][1] += a.y * w.y; acc[1][2] += a.y * w.z; acc[1][3] += a.y * w.w;
            acc[2][0] += a.z * w.x; acc[2][1] += a.z * w.y; acc[2][2] += a.z * w.z; acc[2][3] += a.z * w.w;
            acc[3][0] += a.w * w.x; acc[3][1] += a.w * w.y; acc[3][2] += a.w * w.z; acc[3][3] += a.w * w.w;
        }
    }
#pragma unroll
    for (int i = 0; i < 4; i++) {
        const int r = ty * 4 + i;                         // local t within chunk
        float4 f = *(const float4*)&Fr[r * NOUT + tx * 4];
        float4 o = make_float4(acc[i][0] + f.x, acc[i][1] + f.y,
                               acc[i][2] + f.z, acc[i][3] + f.w);
        *(float4*)&y[(size_t)(m0 + r) * NOUT + tx * 4] = o;
    }
}

// ---------------- launch ----------------
extern "C" void kernel_launch(void* const* d_in, const int* in_sizes, int n_in,
                              void* d_out, int out_size) {
    const float* x   = (const float*)d_in[0];  // [64,4096,64]
    const float* AT  = (const float*)d_in[1];  // [128,128]
    const float* KT  = (const float*)d_in[2];  // [64,128]
    const float* CyT = (const float*)d_in[3];  // [128,64]
    float*       y   = (float*)d_out;          // [64,4096,64]

    float *P2, *P4, *P8, *P16, *P32, *P64, *G2, *E, *F;
    cudaGetSymbolAddress((void**)&P2,  g_P2);
    cudaGetSymbolAddress((void**)&P4,  g_P4);
    cudaGetSymbolAddress((void**)&P8,  g_P8);
    cudaGetSymbolAddress((void**)&P16, g_P16);
    cudaGetSymbolAddress((void**)&P32, g_P32);
    cudaGetSymbolAddress((void**)&P64, g_P64);
    cudaGetSymbolAddress((void**)&G2,  g_G2);
    cudaGetSymbolAddress((void**)&E,   g_e);
    cudaGetSymbolAddress((void**)&F,   g_F);
    const int LD = R * NOUT;  // 4096

    // K1: Ky = x@KT
    k_in_gemm<<<dim3(BT / 64, 2), 256>>>(x, KT);

    // Powers + G[r] = A^(r+1)@CyT by log-doubling (G2 layout: [128][r*64+o])
    gemm_ld<<<dim3(2, 2), 256>>>(AT, AT, 128, P2, 128);            // P2 = A@A
    gemm_ld<<<dim3(1, 2), 256>>>(AT, CyT, 64, G2 + 0 * 64, LD);    // G[0] = A@CyT
    gemm_ld<<<dim3(2, 2), 256>>>(P2, P2, 128, P4, 128);
    gemm_ld<<<dim3(1, 2), 256>>>(AT, G2 + 0, LD, G2 + 1 * 64, LD); // G[1] = A@G[0]
    gemm_ld<<<dim3(2, 2), 256>>>(P4, P4, 128, P8, 128);
    gemm_ld<<<dim3(2, 2), 256>>>(P2, G2 + 0, LD, G2 + 2 * 64, LD); // G[2..3]
    gemm_ld<<<dim3(2, 2), 256>>>(P8, P8, 128, P16, 128);
    gemm_ld<<<dim3(4, 2), 256>>>(P4, G2 + 0, LD, G2 + 4 * 64, LD); // G[4..7]
    gemm_ld<<<dim3(2, 2), 256>>>(P16, P16, 128, P32, 128);
    gemm_ld<<<dim3(8, 2), 256>>>(P8, G2 + 0, LD, G2 + 8 * 64, LD); // G[8..15]
    gemm_ld<<<dim3(2, 2), 256>>>(P32, P32, 128, P64, 128);
    gemm_ld<<<dim3(16, 2), 256>>>(P16, G2 + 0, LD, G2 + 16 * 64, LD); // G[16..31]
    gemm_ld<<<dim3(32, 2), 256>>>(P32, G2 + 0, LD, G2 + 32 * 64, LD); // G[32..63]

    // Local chunk scans (parallel), boundary scan (short serial)
    k_local<<<BCn, 128>>>(AT);
    k_boundary<<<Bc, 128>>>();

    // F = E @ G2   [4096x128]@[128x4096]
    gemm_ld<<<dim3(LD / 64, BCn / 64), 256>>>(E, G2, LD, F, LD);

    // y = sl@CyT + F
    k_out<<<BT / 64, 256>>>(CyT, y);
}